// round 1
// baseline (speedup 1.0000x reference)
#include <cuda_runtime.h>
#include <cuda_bf16.h>
#include <cstdint>

// Problem constants (fixed by the dataset)
#define BB 8
#define CC 512
#define NN 4096
#define DD 64

// Scratch (static device globals — no allocation)
__device__ float g_Qf[BB][DD][NN];     // delu(Q)  8 MB
__device__ float g_Kf[BB][DD][NN];     // delu(K)  8 MB
__device__ float g_Mp[4][BB][DD][CC];  // partial M = Kf @ x^T (4 N-splits) 4 MB
__device__ float g_KV[BB][DD][CC];     // KV = M @ wv^T + Ksum (x) bv
__device__ float g_Ksum[BB][DD];

__device__ __forceinline__ float delu_f(float v) {
    return 10.0f * fmaxf(v, 0.0f) + __expf(10.0f * fminf(v, 0.0f));
}

// ---------------------------------------------------------------------------
// K1: [Wq;Wk] (128x512) @ x[b] (512x4096)  + bias, delu -> g_Qf, g_Kf
// grid (32 n-tiles, 8 batches), 256 threads, 128x128 tile, 8x8 per thread
// ---------------------------------------------------------------------------
__global__ __launch_bounds__(256) void k1_qk(
    const float* __restrict__ x,
    const float* __restrict__ wq, const float* __restrict__ bq,
    const float* __restrict__ wk, const float* __restrict__ bk)
{
    const int b  = blockIdx.y;
    const int n0 = blockIdx.x * 128;
    const int tid = threadIdx.x;
    const int tx = tid & 15, ty = tid >> 4;

    __shared__ float sA[32][132];  // [k][row 0..127]  (rows 0-63 = Q, 64-127 = K)
    __shared__ float sB[32][132];  // [k][n]

    float acc[8][8];
#pragma unroll
    for (int i = 0; i < 8; i++)
#pragma unroll
        for (int j = 0; j < 8; j++) acc[i][j] = 0.f;

    for (int k0 = 0; k0 < CC; k0 += 32) {
        // A: 128 rows x 32 k = 1024 float4
#pragma unroll
        for (int i = 0; i < 4; i++) {
            int idx = tid + i * 256;          // [0,1024)
            int r = idx >> 3;                 // row 0..127
            int kk = (idx & 7) << 2;          // 0,4,..,28
            const float* src = (r < 64) ? (wq + (size_t)r * CC)
                                        : (wk + (size_t)(r - 64) * CC);
            float4 v = *reinterpret_cast<const float4*>(src + k0 + kk);
            sA[kk + 0][r] = v.x; sA[kk + 1][r] = v.y;
            sA[kk + 2][r] = v.z; sA[kk + 3][r] = v.w;
        }
        // B: 32 k-rows x 128 n = 1024 float4 (row-contiguous)
#pragma unroll
        for (int i = 0; i < 4; i++) {
            int idx = tid + i * 256;          // [0,1024)
            int kk = idx >> 5;                // 0..31
            int j  = (idx & 31) << 2;         // 0..124
            float4 v = *reinterpret_cast<const float4*>(
                x + ((size_t)(b * CC + k0 + kk)) * NN + n0 + j);
            *reinterpret_cast<float4*>(&sB[kk][j]) = v;
        }
        __syncthreads();
#pragma unroll
        for (int kk = 0; kk < 32; kk++) {
            float a[8], bb[8];
#pragma unroll
            for (int i = 0; i < 8; i++) a[i]  = sA[kk][ty + i * 16];
#pragma unroll
            for (int j = 0; j < 8; j++) bb[j] = sB[kk][tx + j * 16];
#pragma unroll
            for (int i = 0; i < 8; i++)
#pragma unroll
                for (int j = 0; j < 8; j++) acc[i][j] += a[i] * bb[j];
        }
        __syncthreads();
    }

    // epilogue: bias + delu -> Qf / Kf
#pragma unroll
    for (int i = 0; i < 8; i++) {
        int r = ty + i * 16;
        float bias = (r < 64) ? bq[r] : bk[r - 64];
        float* dst = (r < 64) ? &g_Qf[b][r][0] : &g_Kf[b][r - 64][0];
#pragma unroll
        for (int j = 0; j < 8; j++) {
            int n = n0 + tx + j * 16;
            dst[n] = delu_f(acc[i][j] + bias);
        }
    }
}

// ---------------------------------------------------------------------------
// K2a: Ksum[b][d] = sum_n Kf[b][d][n]    grid (64,8) x 256
// ---------------------------------------------------------------------------
__global__ __launch_bounds__(256) void k2a_ksum()
{
    const int d = blockIdx.x, b = blockIdx.y;
    const float* src = &g_Kf[b][d][0];
    float s = 0.f;
    for (int i = threadIdx.x; i < NN; i += 256) s += src[i];
#pragma unroll
    for (int o = 16; o > 0; o >>= 1) s += __shfl_xor_sync(0xffffffffu, s, o);
    __shared__ float red[8];
    if ((threadIdx.x & 31) == 0) red[threadIdx.x >> 5] = s;
    __syncthreads();
    if (threadIdx.x == 0) {
        float t = 0.f;
#pragma unroll
        for (int w = 0; w < 8; w++) t += red[w];
        g_Ksum[b][d] = t;
    }
}

// ---------------------------------------------------------------------------
// K2: M_part[ns][b][d][c] = sum_{n in split} Kf[b][d][n] * x[b][c][n]
// grid (8 c-tiles, 8 batches, 4 n-splits), 256 threads, 64x64 tile, 4x4/thr
// ---------------------------------------------------------------------------
__global__ __launch_bounds__(256) void k2_m(const float* __restrict__ x)
{
    const int b  = blockIdx.y;
    const int c0 = blockIdx.x * 64;
    const int ns = blockIdx.z;
    const int nbase = ns * 1024;
    const int tid = threadIdx.x;
    const int tx = tid & 15, ty = tid >> 4;

    __shared__ float sK[32][68];  // [n][d]
    __shared__ float sX[32][68];  // [n][c]

    float acc[4][4];
#pragma unroll
    for (int i = 0; i < 4; i++)
#pragma unroll
        for (int j = 0; j < 4; j++) acc[i][j] = 0.f;

    for (int nc = 0; nc < 1024; nc += 32) {
        // Kf tile: 64 d x 32 n = 512 float4
#pragma unroll
        for (int i = 0; i < 2; i++) {
            int idx = tid + i * 256;          // [0,512)
            int d = idx >> 3;
            int nn = (idx & 7) << 2;
            float4 v = *reinterpret_cast<const float4*>(&g_Kf[b][d][nbase + nc + nn]);
            sK[nn + 0][d] = v.x; sK[nn + 1][d] = v.y;
            sK[nn + 2][d] = v.z; sK[nn + 3][d] = v.w;
        }
        // x tile: 64 c x 32 n
#pragma unroll
        for (int i = 0; i < 2; i++) {
            int idx = tid + i * 256;
            int c = idx >> 3;
            int nn = (idx & 7) << 2;
            float4 v = *reinterpret_cast<const float4*>(
                x + ((size_t)(b * CC + c0 + c)) * NN + nbase + nc + nn);
            sX[nn + 0][c] = v.x; sX[nn + 1][c] = v.y;
            sX[nn + 2][c] = v.z; sX[nn + 3][c] = v.w;
        }
        __syncthreads();
#pragma unroll
        for (int nn = 0; nn < 32; nn++) {
            float a[4], bb[4];
#pragma unroll
            for (int i = 0; i < 4; i++) a[i]  = sK[nn][ty + i * 16];
#pragma unroll
            for (int j = 0; j < 4; j++) bb[j] = sX[nn][tx + j * 16];
#pragma unroll
            for (int i = 0; i < 4; i++)
#pragma unroll
                for (int j = 0; j < 4; j++) acc[i][j] += a[i] * bb[j];
        }
        __syncthreads();
    }
#pragma unroll
    for (int i = 0; i < 4; i++)
#pragma unroll
        for (int j = 0; j < 4; j++)
            g_Mp[ns][b][ty + i * 16][c0 + tx + j * 16] = acc[i][j];
}

// ---------------------------------------------------------------------------
// K3: KV[b][m][e] = sum_c (sum_ns Mp[ns][b][m][c]) * wv[e][c] + Ksum[b][m]*bv[e]
// grid (8 e-tiles, 8 batches), 256 threads, 64x64 tile
// ---------------------------------------------------------------------------
__global__ __launch_bounds__(256) void k3_kv(
    const float* __restrict__ wv, const float* __restrict__ bv)
{
    const int b  = blockIdx.y;
    const int e0 = blockIdx.x * 64;
    const int tid = threadIdx.x;
    const int tx = tid & 15, ty = tid >> 4;

    __shared__ float sM[32][68];  // [c][m]
    __shared__ float sW[32][68];  // [c][e]

    float acc[4][4];
#pragma unroll
    for (int i = 0; i < 4; i++)
#pragma unroll
        for (int j = 0; j < 4; j++) acc[i][j] = 0.f;

    for (int cb = 0; cb < CC; cb += 32) {
        // M tile (sum of 4 partials): 64 m x 32 c
#pragma unroll
        for (int i = 0; i < 2; i++) {
            int idx = tid + i * 256;
            int m = idx >> 3;
            int cc = (idx & 7) << 2;
            float4 v0 = *reinterpret_cast<const float4*>(&g_Mp[0][b][m][cb + cc]);
            float4 v1 = *reinterpret_cast<const float4*>(&g_Mp[1][b][m][cb + cc]);
            float4 v2 = *reinterpret_cast<const float4*>(&g_Mp[2][b][m][cb + cc]);
            float4 v3 = *reinterpret_cast<const float4*>(&g_Mp[3][b][m][cb + cc]);
            sM[cc + 0][m] = v0.x + v1.x + v2.x + v3.x;
            sM[cc + 1][m] = v0.y + v1.y + v2.y + v3.y;
            sM[cc + 2][m] = v0.z + v1.z + v2.z + v3.z;
            sM[cc + 3][m] = v0.w + v1.w + v2.w + v3.w;
        }
        // wv tile: 64 e x 32 c
#pragma unroll
        for (int i = 0; i < 2; i++) {
            int idx = tid + i * 256;
            int e = idx >> 3;
            int cc = (idx & 7) << 2;
            float4 v = *reinterpret_cast<const float4*>(
                wv + (size_t)(e0 + e) * CC + cb + cc);
            sW[cc + 0][e] = v.x; sW[cc + 1][e] = v.y;
            sW[cc + 2][e] = v.z; sW[cc + 3][e] = v.w;
        }
        __syncthreads();
#pragma unroll
        for (int cc = 0; cc < 32; cc++) {
            float a[4], bb[4];
#pragma unroll
            for (int i = 0; i < 4; i++) a[i]  = sM[cc][ty + i * 16];
#pragma unroll
            for (int j = 0; j < 4; j++) bb[j] = sW[cc][tx + j * 16];
#pragma unroll
            for (int i = 0; i < 4; i++)
#pragma unroll
                for (int j = 0; j < 4; j++) acc[i][j] += a[i] * bb[j];
        }
        __syncthreads();
    }
#pragma unroll
    for (int i = 0; i < 4; i++) {
        int m = ty + i * 16;
        float ks = g_Ksum[b][m];
#pragma unroll
        for (int j = 0; j < 4; j++) {
            int e = e0 + tx + j * 16;
            g_KV[b][m][e] = acc[i][j] + ks * bv[e];
        }
    }
}

// ---------------------------------------------------------------------------
// K4: out[b][c][n] = x[b][c][n] + gamma * norm[b][n] * sum_d Qf[b][d][n]*KV[b][d][c]
//     norm[b][n] = 1 / sum_d Qf[b][d][n] * (Ksum[b][d] + EPS)
// grid (32 n-tiles, 4 c-tiles, 8 batches), 256 threads, 128x128 tile, 8x8/thr
// dynamic smem: sQ[64][128] + sV[64][128] = 64 KB
// ---------------------------------------------------------------------------
__global__ __launch_bounds__(256) void k4_out(
    const float* __restrict__ x, const float* __restrict__ gamma,
    float* __restrict__ out)
{
    const int b  = blockIdx.z;
    const int n0 = blockIdx.x * 128;
    const int c0 = blockIdx.y * 128;
    const int tid = threadIdx.x;
    const int tx = tid & 15, ty = tid >> 4;

    extern __shared__ float smem[];
    float* sQ = smem;              // [d][n]  64*128
    float* sV = smem + 64 * 128;   // [d][c]  64*128
    __shared__ float snorm[128];
    __shared__ float sKs[64];

    // load Qf tile
#pragma unroll
    for (int i = 0; i < 8; i++) {
        int idx = tid + i * 256;          // [0,2048) float4
        int d = idx >> 5;
        int j = (idx & 31) << 2;
        float4 v = *reinterpret_cast<const float4*>(&g_Qf[b][d][n0 + j]);
        *reinterpret_cast<float4*>(&sQ[d * 128 + j]) = v;
    }
    // load KV tile
#pragma unroll
    for (int i = 0; i < 8; i++) {
        int idx = tid + i * 256;
        int d = idx >> 5;
        int j = (idx & 31) << 2;
        float4 v = *reinterpret_cast<const float4*>(&g_KV[b][d][c0 + j]);
        *reinterpret_cast<float4*>(&sV[d * 128 + j]) = v;
    }
    if (tid < 64) sKs[tid] = g_Ksum[b][tid] + 1e-10f;
    __syncthreads();

    if (tid < 128) {
        float s = 0.f;
#pragma unroll
        for (int d = 0; d < 64; d++) s += sQ[d * 128 + tid] * sKs[d];
        snorm[tid] = 1.0f / s;
    }
    __syncthreads();

    float acc[8][8];
#pragma unroll
    for (int i = 0; i < 8; i++)
#pragma unroll
        for (int j = 0; j < 8; j++) acc[i][j] = 0.f;

#pragma unroll
    for (int d = 0; d < 64; d++) {
        float a[8], bb[8];
#pragma unroll
        for (int i = 0; i < 8; i++) a[i]  = sV[d * 128 + ty + i * 16];  // c
#pragma unroll
        for (int j = 0; j < 8; j++) bb[j] = sQ[d * 128 + tx + j * 16];  // n
#pragma unroll
        for (int i = 0; i < 8; i++)
#pragma unroll
            for (int j = 0; j < 8; j++) acc[i][j] += a[i] * bb[j];
    }

    const float g = gamma[0];
#pragma unroll
    for (int i = 0; i < 8; i++) {
        int c = c0 + ty + i * 16;
#pragma unroll
        for (int j = 0; j < 8; j++) {
            int nl = tx + j * 16;
            size_t off = ((size_t)b * CC + c) * NN + n0 + nl;
            out[off] = x[off] + g * acc[i][j] * snorm[nl];
        }
    }
}

// ---------------------------------------------------------------------------
extern "C" void kernel_launch(void* const* d_in, const int* in_sizes, int n_in,
                              void* d_out, int out_size)
{
    const float* x     = (const float*)d_in[0];
    const float* wq    = (const float*)d_in[1];
    const float* bq    = (const float*)d_in[2];
    const float* wk    = (const float*)d_in[3];
    const float* bk    = (const float*)d_in[4];
    const float* wv    = (const float*)d_in[5];
    const float* bv    = (const float*)d_in[6];
    const float* gamma = (const float*)d_in[7];
    float* out = (float*)d_out;

    static bool attr_set = false;
    if (!attr_set) {
        cudaFuncSetAttribute(k4_out, cudaFuncAttributeMaxDynamicSharedMemorySize,
                             64 * 1024);
        attr_set = true;
    }

    k1_qk<<<dim3(NN / 128, BB), 256>>>(x, wq, bq, wk, bk);
    k2a_ksum<<<dim3(DD, BB), 256>>>();
    k2_m<<<dim3(CC / 64, BB, 4), 256>>>(x);
    k3_kv<<<dim3(CC / 64, BB), 256>>>(wv, bv);
    k4_out<<<dim3(NN / 128, CC / 128, BB), 256, 64 * 1024>>>(x, gamma, out);
}

// round 3
// speedup vs baseline: 2.3195x; 2.3195x over previous
#include <cuda_runtime.h>
#include <cuda_bf16.h>
#include <cstdint>

// Problem constants (fixed by the dataset)
#define BB 8
#define CC 512
#define NN 4096
#define DD 64
#define K2_NS 8   // n-splits for k2

// Scratch (static device globals — no allocation)
__device__ float g_Qf[BB][DD][NN];          // delu(Q)  8 MB
__device__ float g_Kf[BB][DD][NN];          // delu(K)  8 MB
__device__ float g_Mp[K2_NS][BB][CC][DD];   // partial M^T: [ns][b][c][d]
__device__ float g_KVp[4][BB][DD][CC];      // partial KV (c-splits)
__device__ float g_KV[BB][DD][CC];          // KV = M @ wv^T + Ksum (x) bv
__device__ float g_Ksum[BB][DD];

__device__ __forceinline__ float delu_f(float v) {
    return 10.0f * fmaxf(v, 0.0f) + __expf(10.0f * fminf(v, 0.0f));
}

// round-to-nearest tf32 (keeps fp32 container, low mantissa bits cleared)
__device__ __forceinline__ float tf32r(float f) {
    uint32_t u;
    asm("cvt.rna.tf32.f32 %0, %1;" : "=r"(u) : "f"(f));
    return __uint_as_float(u);
}

// D += A(16x8) * B(8x8), tf32 inputs, f32 accum
__device__ __forceinline__ void mma_tf32(float4& d,
                                         uint32_t a0, uint32_t a1, uint32_t a2, uint32_t a3,
                                         uint32_t b0, uint32_t b1) {
    asm volatile(
        "mma.sync.aligned.m16n8k8.row.col.f32.tf32.tf32.f32 "
        "{%0,%1,%2,%3}, {%4,%5,%6,%7}, {%8,%9}, {%0,%1,%2,%3};"
        : "+f"(d.x), "+f"(d.y), "+f"(d.z), "+f"(d.w)
        : "r"(a0), "r"(a1), "r"(a2), "r"(a3), "r"(b0), "r"(b1));
}

// ---------------------------------------------------------------------------
// K1 (mma): [Wq;Wk](128x512) @ x[b](512x4096) + bias, delu -> g_Qf, g_Kf
// grid (32 n-tiles, 8 b), 256 thr (8 warps). Block tile 128m x 128n, K-chunk 32.
// Warp tile 32m x 64n. smem: sA[m][k] pad36, sB[k][n] pad132, tf32-rounded.
// ---------------------------------------------------------------------------
__global__ __launch_bounds__(256) void k1_qk(
    const float* __restrict__ x,
    const float* __restrict__ wq, const float* __restrict__ bq,
    const float* __restrict__ wk, const float* __restrict__ bk)
{
    const int b  = blockIdx.y;
    const int n0 = blockIdx.x * 128;
    const int tid = threadIdx.x;
    const int wid = tid >> 5, lane = tid & 31;
    const int g = lane >> 2, tig = lane & 3;
    const int wm0 = (wid >> 1) * 32;
    const int wn0 = (wid & 1) * 64;

    __shared__ float sA[128 * 36];   // [m][k] stride 36
    __shared__ float sB[32 * 132];   // [k][n] stride 132
    const uint32_t* sAu = reinterpret_cast<const uint32_t*>(sA);
    const uint32_t* sBu = reinterpret_cast<const uint32_t*>(sB);

    float4 acc[2][8];
#pragma unroll
    for (int i = 0; i < 2; i++)
#pragma unroll
        for (int j = 0; j < 8; j++) acc[i][j] = make_float4(0.f, 0.f, 0.f, 0.f);

    for (int k0 = 0; k0 < CC; k0 += 32) {
        // A: 128 rows x 32 k (1024 float4)
#pragma unroll
        for (int i = 0; i < 4; i++) {
            int idx = tid + i * 256;
            int r = idx >> 3;
            int kk = (idx & 7) << 2;
            const float* src = (r < 64) ? (wq + (size_t)r * CC)
                                        : (wk + (size_t)(r - 64) * CC);
            float4 v = *reinterpret_cast<const float4*>(src + k0 + kk);
            v.x = tf32r(v.x); v.y = tf32r(v.y); v.z = tf32r(v.z); v.w = tf32r(v.w);
            *reinterpret_cast<float4*>(&sA[r * 36 + kk]) = v;
        }
        // B: 32 k x 128 n (1024 float4)
#pragma unroll
        for (int i = 0; i < 4; i++) {
            int idx = tid + i * 256;
            int kk = idx >> 5;
            int j  = (idx & 31) << 2;
            float4 v = *reinterpret_cast<const float4*>(
                x + ((size_t)(b * CC + k0 + kk)) * NN + n0 + j);
            v.x = tf32r(v.x); v.y = tf32r(v.y); v.z = tf32r(v.z); v.w = tf32r(v.w);
            *reinterpret_cast<float4*>(&sB[kk * 132 + j]) = v;
        }
        __syncthreads();
#pragma unroll
        for (int ks = 0; ks < 32; ks += 8) {
            uint32_t a[2][4];
#pragma unroll
            for (int i = 0; i < 2; i++) {
                int r = wm0 + i * 16 + g;
                a[i][0] = sAu[r * 36 + ks + tig];
                a[i][1] = sAu[(r + 8) * 36 + ks + tig];
                a[i][2] = sAu[r * 36 + ks + tig + 4];
                a[i][3] = sAu[(r + 8) * 36 + ks + tig + 4];
            }
#pragma unroll
            for (int j = 0; j < 8; j++) {
                int n = wn0 + j * 8 + g;
                uint32_t b0 = sBu[(ks + tig) * 132 + n];
                uint32_t b1 = sBu[(ks + tig + 4) * 132 + n];
#pragma unroll
                for (int i = 0; i < 2; i++)
                    mma_tf32(acc[i][j], a[i][0], a[i][1], a[i][2], a[i][3], b0, b1);
            }
        }
        __syncthreads();
    }

    // epilogue: bias + delu -> Qf / Kf  (rows r and r+8 share the same 64-half)
#pragma unroll
    for (int i = 0; i < 2; i++) {
        int r0 = wm0 + i * 16 + g;
        int r1 = r0 + 8;
        float bias0 = (r0 < 64) ? bq[r0] : bk[r0 - 64];
        float bias1 = (r1 < 64) ? bq[r1] : bk[r1 - 64];
        float* dst0 = (r0 < 64) ? &g_Qf[b][r0][0] : &g_Kf[b][r0 - 64][0];
        float* dst1 = (r1 < 64) ? &g_Qf[b][r1][0] : &g_Kf[b][r1 - 64][0];
#pragma unroll
        for (int j = 0; j < 8; j++) {
            int n = n0 + wn0 + j * 8 + 2 * tig;
            float2 o0 = make_float2(delu_f(acc[i][j].x + bias0), delu_f(acc[i][j].y + bias0));
            float2 o1 = make_float2(delu_f(acc[i][j].z + bias1), delu_f(acc[i][j].w + bias1));
            *reinterpret_cast<float2*>(dst0 + n) = o0;
            *reinterpret_cast<float2*>(dst1 + n) = o1;
        }
    }
}

// ---------------------------------------------------------------------------
// K2a: Ksum[b][d] = sum_n Kf[b][d][n]
// ---------------------------------------------------------------------------
__global__ __launch_bounds__(256) void k2a_ksum()
{
    const int d = blockIdx.x, b = blockIdx.y;
    const float* src = &g_Kf[b][d][0];
    float s = 0.f;
    for (int i = threadIdx.x; i < NN; i += 256) s += src[i];
#pragma unroll
    for (int o = 16; o > 0; o >>= 1) s += __shfl_xor_sync(0xffffffffu, s, o);
    __shared__ float red[8];
    if ((threadIdx.x & 31) == 0) red[threadIdx.x >> 5] = s;
    __syncthreads();
    if (threadIdx.x == 0) {
        float t = 0.f;
#pragma unroll
        for (int w = 0; w < 8; w++) t += red[w];
        g_Ksum[b][d] = t;
    }
}

// ---------------------------------------------------------------------------
// K2 (mma): Mp[ns][b][c][d] = sum_{n in split} x[b][c][n] * Kf[b][d][n]
// A = x[c][n] row-major (m=c,k=n); B col-frag = Kf[d][n] natural.
// grid (4 c-tiles, 8 b, 8 ns) = 256 blocks, 256 thr. Tile 128c x 64d, K-chunk 32.
// Warp tile 32c x 32d. smem: sX[c][k] pad36, sK[d][k] pad36.
// ---------------------------------------------------------------------------
__global__ __launch_bounds__(256) void k2_mma(const float* __restrict__ x)
{
    const int b  = blockIdx.y;
    const int c0 = blockIdx.x * 128;
    const int ns = blockIdx.z;
    const int nbase = ns * (NN / K2_NS);       // 512 per split
    const int tid = threadIdx.x;
    const int wid = tid >> 5, lane = tid & 31;
    const int g = lane >> 2, tig = lane & 3;
    const int wc0 = (wid >> 1) * 32;
    const int wd0 = (wid & 1) * 32;

    __shared__ float sX[128 * 36];
    __shared__ float sK[64 * 36];
    const uint32_t* sXu = reinterpret_cast<const uint32_t*>(sX);
    const uint32_t* sKu = reinterpret_cast<const uint32_t*>(sK);

    float4 acc[2][4];
#pragma unroll
    for (int i = 0; i < 2; i++)
#pragma unroll
        for (int j = 0; j < 4; j++) acc[i][j] = make_float4(0.f, 0.f, 0.f, 0.f);

    for (int nc = 0; nc < NN / K2_NS; nc += 32) {
        const int nb = nbase + nc;
        // x tile: 128 c x 32 n
#pragma unroll
        for (int i = 0; i < 4; i++) {
            int idx = tid + i * 256;
            int r = idx >> 3;
            int kk = (idx & 7) << 2;
            float4 v = *reinterpret_cast<const float4*>(
                x + ((size_t)(b * CC + c0 + r)) * NN + nb + kk);
            v.x = tf32r(v.x); v.y = tf32r(v.y); v.z = tf32r(v.z); v.w = tf32r(v.w);
            *reinterpret_cast<float4*>(&sX[r * 36 + kk]) = v;
        }
        // Kf tile: 64 d x 32 n
#pragma unroll
        for (int i = 0; i < 2; i++) {
            int idx = tid + i * 256;
            int r = idx >> 3;
            int kk = (idx & 7) << 2;
            float4 v = *reinterpret_cast<const float4*>(&g_Kf[b][r][nb + kk]);
            v.x = tf32r(v.x); v.y = tf32r(v.y); v.z = tf32r(v.z); v.w = tf32r(v.w);
            *reinterpret_cast<float4*>(&sK[r * 36 + kk]) = v;
        }
        __syncthreads();
#pragma unroll
        for (int ks = 0; ks < 32; ks += 8) {
            uint32_t a[2][4];
#pragma unroll
            for (int i = 0; i < 2; i++) {
                int r = wc0 + i * 16 + g;
                a[i][0] = sXu[r * 36 + ks + tig];
                a[i][1] = sXu[(r + 8) * 36 + ks + tig];
                a[i][2] = sXu[r * 36 + ks + tig + 4];
                a[i][3] = sXu[(r + 8) * 36 + ks + tig + 4];
            }
#pragma unroll
            for (int j = 0; j < 4; j++) {
                int d = wd0 + j * 8 + g;
                uint32_t b0 = sKu[d * 36 + ks + tig];
                uint32_t b1 = sKu[d * 36 + ks + tig + 4];
#pragma unroll
                for (int i = 0; i < 2; i++)
                    mma_tf32(acc[i][j], a[i][0], a[i][1], a[i][2], a[i][3], b0, b1);
            }
        }
        __syncthreads();
    }
#pragma unroll
    for (int i = 0; i < 2; i++) {
        int r0 = c0 + wc0 + i * 16 + g;
#pragma unroll
        for (int j = 0; j < 4; j++) {
            int d = wd0 + j * 8 + 2 * tig;
            *reinterpret_cast<float2*>(&g_Mp[ns][b][r0][d])     = make_float2(acc[i][j].x, acc[i][j].y);
            *reinterpret_cast<float2*>(&g_Mp[ns][b][r0 + 8][d]) = make_float2(acc[i][j].z, acc[i][j].w);
        }
    }
}

// ---------------------------------------------------------------------------
// K3: KVp[cs][b][m][e] = sum_{c in split} Msum[c][m] * wv[e][c]
// grid (8 e-tiles, 8 b, 4 c-splits), 256 thr, 64x64 tile (scalar FFMA)
// ---------------------------------------------------------------------------
__global__ __launch_bounds__(256) void k3_kv(const float* __restrict__ wv)
{
    const int b  = blockIdx.y;
    const int e0 = blockIdx.x * 64;
    const int cs = blockIdx.z;
    const int cb0 = cs * 128;
    const int tid = threadIdx.x;
    const int tx = tid & 15, ty = tid >> 4;

    __shared__ float sM[32][68];  // [c][m]
    __shared__ float sW[32][68];  // [c][e]

    float acc[4][4];
#pragma unroll
    for (int i = 0; i < 4; i++)
#pragma unroll
        for (int j = 0; j < 4; j++) acc[i][j] = 0.f;

    for (int cb = 0; cb < 128; cb += 32) {
        const int ca = cb0 + cb;
#pragma unroll
        for (int i = 0; i < 2; i++) {
            int idx = tid + i * 256;
            int cc = idx >> 4;
            int mm = (idx & 15) << 2;
            float4 s = make_float4(0.f, 0.f, 0.f, 0.f);
#pragma unroll
            for (int ns = 0; ns < K2_NS; ns++) {
                float4 v = *reinterpret_cast<const float4*>(&g_Mp[ns][b][ca + cc][mm]);
                s.x += v.x; s.y += v.y; s.z += v.z; s.w += v.w;
            }
            *reinterpret_cast<float4*>(&sM[cc][mm]) = s;
        }
#pragma unroll
        for (int i = 0; i < 2; i++) {
            int idx = tid + i * 256;
            int e = idx >> 3;
            int cc = (idx & 7) << 2;
            float4 v = *reinterpret_cast<const float4*>(
                wv + (size_t)(e0 + e) * CC + ca + cc);
            sW[cc + 0][e] = v.x; sW[cc + 1][e] = v.y;
            sW[cc + 2][e] = v.z; sW[cc + 3][e] = v.w;
        }
        __syncthreads();
#pragma unroll
        for (int cc = 0; cc < 32; cc++) {
            float a[4], bb[4];
#pragma unroll
            for (int i = 0; i < 4; i++) a[i]  = sM[cc][ty + i * 16];
#pragma unroll
            for (int j = 0; j < 4; j++) bb[j] = sW[cc][tx + j * 16];
#pragma unroll
            for (int i = 0; i < 4; i++)
#pragma unroll
                for (int j = 0; j < 4; j++) acc[i][j] += a[i] * bb[j];
        }
        __syncthreads();
    }
#pragma unroll
    for (int i = 0; i < 4; i++)
#pragma unroll
        for (int j = 0; j < 4; j++)
            g_KVp[cs][b][ty + i * 16][e0 + tx + j * 16] = acc[i][j];
}

// ---------------------------------------------------------------------------
// K3b: KV = sum_cs KVp + Ksum (x) bv
// ---------------------------------------------------------------------------
__global__ __launch_bounds__(256) void k3b_merge(const float* __restrict__ bv)
{
    const int f = blockIdx.x * 256 + threadIdx.x;
    const int b = f >> 13;
    const int r = f & 8191;
    const int m = r >> 7;
    const int e4 = (r & 127) << 2;

    float4 s0 = *reinterpret_cast<const float4*>(&g_KVp[0][b][m][e4]);
    float4 s1 = *reinterpret_cast<const float4*>(&g_KVp[1][b][m][e4]);
    float4 s2 = *reinterpret_cast<const float4*>(&g_KVp[2][b][m][e4]);
    float4 s3 = *reinterpret_cast<const float4*>(&g_KVp[3][b][m][e4]);
    float4 bb = *reinterpret_cast<const float4*>(bv + e4);
    const float ks = g_Ksum[b][m];
    float4 o;
    o.x = s0.x + s1.x + s2.x + s3.x + ks * bb.x;
    o.y = s0.y + s1.y + s2.y + s3.y + ks * bb.y;
    o.z = s0.z + s1.z + s2.z + s3.z + ks * bb.z;
    o.w = s0.w + s1.w + s2.w + s3.w + ks * bb.w;
    *reinterpret_cast<float4*>(&g_KV[b][m][e4]) = o;
}

// ---------------------------------------------------------------------------
// K4 (mma): out[b][c][n] = x + gamma * norm[n] * sum_d Qf[d][n]*KV[d][c]
// A = KV^T (m=c,k=d) read from sV[d][c]; B col-frag = Qf[d][n] from sQ[d][n].
// grid (32 n-tiles, 4 c-tiles, 8 b), 256 thr. Tile 128c x 128n, K=64.
// dyn smem: sQ[64][132] + sV[64][132] = 66 KB (tf32-rounded)
// ---------------------------------------------------------------------------
__global__ __launch_bounds__(256) void k4_out(
    const float* __restrict__ x, const float* __restrict__ gamma,
    float* __restrict__ out)
{
    const int b  = blockIdx.z;
    const int n0 = blockIdx.x * 128;
    const int c0 = blockIdx.y * 128;
    const int tid = threadIdx.x;
    const int wid = tid >> 5, lane = tid & 31;
    const int g = lane >> 2, tig = lane & 3;
    const int wc0 = (wid >> 1) * 32;
    const int wn0 = (wid & 1) * 64;

    extern __shared__ float smem[];
    float* sQ = smem;               // [d][n] stride 132
    float* sV = smem + 64 * 132;    // [d][c] stride 132
    const uint32_t* sQu = reinterpret_cast<const uint32_t*>(sQ);
    const uint32_t* sVu = reinterpret_cast<const uint32_t*>(sV);
    __shared__ float snorm[128];
    __shared__ float sKs[64];

#pragma unroll
    for (int i = 0; i < 8; i++) {
        int idx = tid + i * 256;
        int d = idx >> 5;
        int j = (idx & 31) << 2;
        float4 v = *reinterpret_cast<const float4*>(&g_Qf[b][d][n0 + j]);
        v.x = tf32r(v.x); v.y = tf32r(v.y); v.z = tf32r(v.z); v.w = tf32r(v.w);
        *reinterpret_cast<float4*>(&sQ[d * 132 + j]) = v;
    }
#pragma unroll
    for (int i = 0; i < 8; i++) {
        int idx = tid + i * 256;
        int d = idx >> 5;
        int j = (idx & 31) << 2;
        float4 v = *reinterpret_cast<const float4*>(&g_KV[b][d][c0 + j]);
        v.x = tf32r(v.x); v.y = tf32r(v.y); v.z = tf32r(v.z); v.w = tf32r(v.w);
        *reinterpret_cast<float4*>(&sV[d * 132 + j]) = v;
    }
    if (tid < 64) sKs[tid] = g_Ksum[b][tid] + 1e-10f;
    __syncthreads();

    if (tid < 128) {
        float s = 0.f;
#pragma unroll
        for (int d = 0; d < 64; d++) s += sQ[d * 132 + tid] * sKs[d];
        snorm[tid] = 1.0f / s;
    }
    __syncthreads();

    float4 acc[2][8];
#pragma unroll
    for (int i = 0; i < 2; i++)
#pragma unroll
        for (int j = 0; j < 8; j++) acc[i][j] = make_float4(0.f, 0.f, 0.f, 0.f);

#pragma unroll
    for (int ks = 0; ks < 64; ks += 8) {
        uint32_t a[2][4];
#pragma unroll
        for (int i = 0; i < 2; i++) {
            int r = wc0 + i * 16 + g;
            a[i][0] = sVu[(ks + tig) * 132 + r];
            a[i][1] = sVu[(ks + tig) * 132 + r + 8];
            a[i][2] = sVu[(ks + tig + 4) * 132 + r];
            a[i][3] = sVu[(ks + tig + 4) * 132 + r + 8];
        }
#pragma unroll
        for (int j = 0; j < 8; j++) {
            int n = wn0 + j * 8 + g;
            uint32_t b0 = sQu[(ks + tig) * 132 + n];
            uint32_t b1 = sQu[(ks + tig + 4) * 132 + n];
#pragma unroll
            for (int i = 0; i < 2; i++)
                mma_tf32(acc[i][j], a[i][0], a[i][1], a[i][2], a[i][3], b0, b1);
        }
    }

    const float gm = gamma[0];
#pragma unroll
    for (int i = 0; i < 2; i++) {
        int r0 = c0 + wc0 + i * 16 + g;
        int r1 = r0 + 8;
#pragma unroll
        for (int j = 0; j < 8; j++) {
            int nl = wn0 + j * 8 + 2 * tig;
            float nm0 = snorm[nl], nm1 = snorm[nl + 1];
            size_t off0 = ((size_t)b * CC + r0) * NN + n0 + nl;
            size_t off1 = ((size_t)b * CC + r1) * NN + n0 + nl;
            float2 x0 = *reinterpret_cast<const float2*>(x + off0);
            float2 x1 = *reinterpret_cast<const float2*>(x + off1);
            float2 o0 = make_float2(x0.x + gm * acc[i][j].x * nm0,
                                    x0.y + gm * acc[i][j].y * nm1);
            float2 o1 = make_float2(x1.x + gm * acc[i][j].z * nm0,
                                    x1.y + gm * acc[i][j].w * nm1);
            *reinterpret_cast<float2*>(out + off0) = o0;
            *reinterpret_cast<float2*>(out + off1) = o1;
        }
    }
}

// ---------------------------------------------------------------------------
extern "C" void kernel_launch(void* const* d_in, const int* in_sizes, int n_in,
                              void* d_out, int out_size)
{
    const float* x     = (const float*)d_in[0];
    const float* wq    = (const float*)d_in[1];
    const float* bq    = (const float*)d_in[2];
    const float* wk    = (const float*)d_in[3];
    const float* bk    = (const float*)d_in[4];
    const float* wv    = (const float*)d_in[5];
    const float* bv    = (const float*)d_in[6];
    const float* gamma = (const float*)d_in[7];
    float* out = (float*)d_out;

    static bool attr_set = false;
    if (!attr_set) {
        cudaFuncSetAttribute(k4_out, cudaFuncAttributeMaxDynamicSharedMemorySize,
                             2 * 64 * 132 * 4);
        attr_set = true;
    }

    k1_qk<<<dim3(NN / 128, BB), 256>>>(x, wq, bq, wk, bk);
    k2a_ksum<<<dim3(DD, BB), 256>>>();
    k2_mma<<<dim3(CC / 128, BB, K2_NS), 256>>>(x);
    k3_kv<<<dim3(CC / 64, BB, 4), 256>>>(wv);
    k3b_merge<<<256, 256>>>(bv);
    k4_out<<<dim3(NN / 128, CC / 128, BB), 256, 2 * 64 * 132 * 4>>>(x, gamma, out);
}

// round 4
// speedup vs baseline: 2.8992x; 1.2499x over previous
#include <cuda_runtime.h>
#include <cuda_bf16.h>
#include <cstdint>

// Problem constants (fixed by the dataset)
#define BB 8
#define CC 512
#define NN 4096
#define DD 64
#define K2_NS 8   // n-splits for k2

// Scratch (static device globals — no allocation)
__device__ float g_Qf[BB][DD][NN];          // delu(Q)  8 MB
__device__ float g_Kf[BB][DD][NN];          // delu(K)  8 MB
__device__ float g_Mp[K2_NS][BB][CC][DD];   // partial M^T: [ns][b][c][d]
__device__ float g_Msum[BB][CC][DD];        // summed M^T
__device__ float g_KVp[4][BB][DD][CC];      // partial KV (c-splits)
__device__ float g_KV[BB][DD][CC];          // KV = M @ wv^T + Ksum (x) bv
__device__ float g_Ksum[BB][DD];

__device__ __forceinline__ float delu_f(float v) {
    return 10.0f * fmaxf(v, 0.0f) + __expf(10.0f * fminf(v, 0.0f));
}

__device__ __forceinline__ uint32_t smem_u32(const void* p) {
    uint32_t a;
    asm("{ .reg .u64 t; cvta.to.shared.u64 t, %1; cvt.u32.u64 %0, t; }"
        : "=r"(a) : "l"(p));
    return a;
}

#define CP16(dst, src) \
    asm volatile("cp.async.cg.shared.global [%0], [%1], 16;" :: "r"(dst), "l"(src))
#define CP_COMMIT() asm volatile("cp.async.commit_group;" ::: "memory")
#define CP_WAIT1()  asm volatile("cp.async.wait_group 1;" ::: "memory")
#define CP_WAIT0()  asm volatile("cp.async.wait_group 0;" ::: "memory")

// D += A(16x8) * B(8x8), tf32 inputs (fp32 bits, HW-truncated), f32 accum
__device__ __forceinline__ void mma_tf32(float4& d,
                                         uint32_t a0, uint32_t a1, uint32_t a2, uint32_t a3,
                                         uint32_t b0, uint32_t b1) {
    asm volatile(
        "mma.sync.aligned.m16n8k8.row.col.f32.tf32.tf32.f32 "
        "{%0,%1,%2,%3}, {%4,%5,%6,%7}, {%8,%9}, {%0,%1,%2,%3};"
        : "+f"(d.x), "+f"(d.y), "+f"(d.z), "+f"(d.w)
        : "r"(a0), "r"(a1), "r"(a2), "r"(a3), "r"(b0), "r"(b1));
}

// ---------------------------------------------------------------------------
// K1 (mma + cp.async 2-stage): [Wq;Wk](128x512) @ x[b](512x4096) + bias, delu
// grid (32 n-tiles, 8 b), 256 thr. Tile 128m x 128n, K-chunk 32.
// smem (dynamic): sA[2][128*36] (A-frag, stride 36) + sB[2][32*136] (B-frag, 136)
// ---------------------------------------------------------------------------
#define K1_ABUF (128 * 36)
#define K1_BBUF (32 * 136)
#define K1_SMEM ((2 * K1_ABUF + 2 * K1_BBUF) * 4)

__global__ __launch_bounds__(256) void k1_qk(
    const float* __restrict__ x,
    const float* __restrict__ wq, const float* __restrict__ bq,
    const float* __restrict__ wk, const float* __restrict__ bk)
{
    const int b  = blockIdx.y;
    const int n0 = blockIdx.x * 128;
    const int tid = threadIdx.x;
    const int wid = tid >> 5, lane = tid & 31;
    const int g = lane >> 2, tig = lane & 3;
    const int wm0 = (wid >> 1) * 32;
    const int wn0 = (wid & 1) * 64;

    extern __shared__ float dsm[];
    float* sA = dsm;
    float* sB = dsm + 2 * K1_ABUF;
    const uint32_t sA_addr = smem_u32(sA);
    const uint32_t sB_addr = smem_u32(sB);
    const uint32_t* sAu = reinterpret_cast<const uint32_t*>(sA);
    const uint32_t* sBu = reinterpret_cast<const uint32_t*>(sB);

    float4 acc[2][8];
#pragma unroll
    for (int i = 0; i < 2; i++)
#pragma unroll
        for (int j = 0; j < 8; j++) acc[i][j] = make_float4(0.f, 0.f, 0.f, 0.f);

#define K1_ISSUE(ch) do {                                                        \
    const int k0_ = (ch) * 32; const int buf_ = (ch) & 1;                        \
    _Pragma("unroll")                                                            \
    for (int i = 0; i < 4; i++) {                                                \
        int idx = tid + i * 256;                                                 \
        int r = idx >> 3; int kk = (idx & 7) << 2;                               \
        const float* src = (r < 64) ? (wq + (size_t)r * CC + k0_ + kk)           \
                                    : (wk + (size_t)(r - 64) * CC + k0_ + kk);   \
        CP16(sA_addr + (uint32_t)(buf_ * K1_ABUF + r * 36 + kk) * 4, src);       \
    }                                                                            \
    _Pragma("unroll")                                                            \
    for (int i = 0; i < 4; i++) {                                                \
        int idx = tid + i * 256;                                                 \
        int kk = idx >> 5; int j = (idx & 31) << 2;                              \
        const float* src = x + ((size_t)(b * CC + k0_ + kk)) * NN + n0 + j;      \
        CP16(sB_addr + (uint32_t)(buf_ * K1_BBUF + kk * 136 + j) * 4, src);      \
    }                                                                            \
    CP_COMMIT();                                                                 \
} while (0)

    K1_ISSUE(0);
    for (int ch = 0; ch < 16; ch++) {
        if (ch < 15) { K1_ISSUE(ch + 1); CP_WAIT1(); } else { CP_WAIT0(); }
        __syncthreads();
        const uint32_t* A = sAu + (ch & 1) * K1_ABUF;
        const uint32_t* Bm = sBu + (ch & 1) * K1_BBUF;
#pragma unroll
        for (int ks = 0; ks < 32; ks += 8) {
            uint32_t a[2][4];
#pragma unroll
            for (int i = 0; i < 2; i++) {
                int r = wm0 + i * 16 + g;
                a[i][0] = A[r * 36 + ks + tig];
                a[i][1] = A[(r + 8) * 36 + ks + tig];
                a[i][2] = A[r * 36 + ks + tig + 4];
                a[i][3] = A[(r + 8) * 36 + ks + tig + 4];
            }
#pragma unroll
            for (int j = 0; j < 8; j++) {
                int n = wn0 + j * 8 + g;
                uint32_t b0 = Bm[(ks + tig) * 136 + n];
                uint32_t b1 = Bm[(ks + tig + 4) * 136 + n];
#pragma unroll
                for (int i = 0; i < 2; i++)
                    mma_tf32(acc[i][j], a[i][0], a[i][1], a[i][2], a[i][3], b0, b1);
            }
        }
        __syncthreads();
    }

    // epilogue: bias + delu -> Qf / Kf
#pragma unroll
    for (int i = 0; i < 2; i++) {
        int r0 = wm0 + i * 16 + g;
        int r1 = r0 + 8;
        float bias0 = (r0 < 64) ? bq[r0] : bk[r0 - 64];
        float bias1 = (r1 < 64) ? bq[r1] : bk[r1 - 64];
        float* dst0 = (r0 < 64) ? &g_Qf[b][r0][0] : &g_Kf[b][r0 - 64][0];
        float* dst1 = (r1 < 64) ? &g_Qf[b][r1][0] : &g_Kf[b][r1 - 64][0];
#pragma unroll
        for (int j = 0; j < 8; j++) {
            int n = n0 + wn0 + j * 8 + 2 * tig;
            float2 o0 = make_float2(delu_f(acc[i][j].x + bias0), delu_f(acc[i][j].y + bias0));
            float2 o1 = make_float2(delu_f(acc[i][j].z + bias1), delu_f(acc[i][j].w + bias1));
            *reinterpret_cast<float2*>(dst0 + n) = o0;
            *reinterpret_cast<float2*>(dst1 + n) = o1;
        }
    }
}

// ---------------------------------------------------------------------------
// K2a: Ksum[b][d] = sum_n Kf[b][d][n]
// ---------------------------------------------------------------------------
__global__ __launch_bounds__(256) void k2a_ksum()
{
    const int d = blockIdx.x, b = blockIdx.y;
    const float* src = &g_Kf[b][d][0];
    float s = 0.f;
    for (int i = threadIdx.x; i < NN; i += 256) s += src[i];
#pragma unroll
    for (int o = 16; o > 0; o >>= 1) s += __shfl_xor_sync(0xffffffffu, s, o);
    __shared__ float red[8];
    if ((threadIdx.x & 31) == 0) red[threadIdx.x >> 5] = s;
    __syncthreads();
    if (threadIdx.x == 0) {
        float t = 0.f;
#pragma unroll
        for (int w = 0; w < 8; w++) t += red[w];
        g_Ksum[b][d] = t;
    }
}

// ---------------------------------------------------------------------------
// K2 (mma + cp.async 2-stage): Mp[ns][b][c][d] = sum_n x[b][c][n]*Kf[b][d][n]
// grid (4 c-tiles, 8 b, 8 ns) = 256 blocks, 256 thr. Tile 128c x 64d, K-chunk 32.
// smem (dynamic): sX[2][128*36] + sK[2][64*36]
// ---------------------------------------------------------------------------
#define K2_XBUF (128 * 36)
#define K2_KBUF (64 * 36)
#define K2_SMEM ((2 * K2_XBUF + 2 * K2_KBUF) * 4)

__global__ __launch_bounds__(256) void k2_mma(const float* __restrict__ x)
{
    const int b  = blockIdx.y;
    const int c0 = blockIdx.x * 128;
    const int ns = blockIdx.z;
    const int nbase = ns * (NN / K2_NS);       // 512 per split
    const int tid = threadIdx.x;
    const int wid = tid >> 5, lane = tid & 31;
    const int g = lane >> 2, tig = lane & 3;
    const int wc0 = (wid >> 1) * 32;
    const int wd0 = (wid & 1) * 32;

    extern __shared__ float dsm[];
    float* sX = dsm;
    float* sK = dsm + 2 * K2_XBUF;
    const uint32_t sX_addr = smem_u32(sX);
    const uint32_t sK_addr = smem_u32(sK);
    const uint32_t* sXu = reinterpret_cast<const uint32_t*>(sX);
    const uint32_t* sKu = reinterpret_cast<const uint32_t*>(sK);

    float4 acc[2][4];
#pragma unroll
    for (int i = 0; i < 2; i++)
#pragma unroll
        for (int j = 0; j < 4; j++) acc[i][j] = make_float4(0.f, 0.f, 0.f, 0.f);

#define K2_ISSUE(ch) do {                                                        \
    const int nb_ = nbase + (ch) * 32; const int buf_ = (ch) & 1;                \
    _Pragma("unroll")                                                            \
    for (int i = 0; i < 4; i++) {                                                \
        int idx = tid + i * 256;                                                 \
        int r = idx >> 3; int kk = (idx & 7) << 2;                               \
        const float* src = x + ((size_t)(b * CC + c0 + r)) * NN + nb_ + kk;      \
        CP16(sX_addr + (uint32_t)(buf_ * K2_XBUF + r * 36 + kk) * 4, src);       \
    }                                                                            \
    _Pragma("unroll")                                                            \
    for (int i = 0; i < 2; i++) {                                                \
        int idx = tid + i * 256;                                                 \
        int r = idx >> 3; int kk = (idx & 7) << 2;                               \
        const float* src = &g_Kf[b][r][nb_ + kk];                                \
        CP16(sK_addr + (uint32_t)(buf_ * K2_KBUF + r * 36 + kk) * 4, src);       \
    }                                                                            \
    CP_COMMIT();                                                                 \
} while (0)

    K2_ISSUE(0);
    for (int ch = 0; ch < 16; ch++) {
        if (ch < 15) { K2_ISSUE(ch + 1); CP_WAIT1(); } else { CP_WAIT0(); }
        __syncthreads();
        const uint32_t* X = sXu + (ch & 1) * K2_XBUF;
        const uint32_t* Km = sKu + (ch & 1) * K2_KBUF;
#pragma unroll
        for (int ks = 0; ks < 32; ks += 8) {
            uint32_t a[2][4];
#pragma unroll
            for (int i = 0; i < 2; i++) {
                int r = wc0 + i * 16 + g;
                a[i][0] = X[r * 36 + ks + tig];
                a[i][1] = X[(r + 8) * 36 + ks + tig];
                a[i][2] = X[r * 36 + ks + tig + 4];
                a[i][3] = X[(r + 8) * 36 + ks + tig + 4];
            }
#pragma unroll
            for (int j = 0; j < 4; j++) {
                int d = wd0 + j * 8 + g;
                uint32_t b0 = Km[d * 36 + ks + tig];
                uint32_t b1 = Km[d * 36 + ks + tig + 4];
#pragma unroll
                for (int i = 0; i < 2; i++)
                    mma_tf32(acc[i][j], a[i][0], a[i][1], a[i][2], a[i][3], b0, b1);
            }
        }
        __syncthreads();
    }
#pragma unroll
    for (int i = 0; i < 2; i++) {
        int r0 = c0 + wc0 + i * 16 + g;
#pragma unroll
        for (int j = 0; j < 4; j++) {
            int d = wd0 + j * 8 + 2 * tig;
            *reinterpret_cast<float2*>(&g_Mp[ns][b][r0][d])     = make_float2(acc[i][j].x, acc[i][j].y);
            *reinterpret_cast<float2*>(&g_Mp[ns][b][r0 + 8][d]) = make_float2(acc[i][j].z, acc[i][j].w);
        }
    }
}

// ---------------------------------------------------------------------------
// K2b: Msum = sum_ns Mp.  64K float4; grid 256 x 256
// ---------------------------------------------------------------------------
__global__ __launch_bounds__(256) void k2b_msum()
{
    const int f = blockIdx.x * 256 + threadIdx.x;   // 0..65535
    const int b = f >> 13;
    const int r = f & 8191;
    const int c = r >> 4;
    const int d4 = (r & 15) << 2;

    float4 s = make_float4(0.f, 0.f, 0.f, 0.f);
#pragma unroll
    for (int ns = 0; ns < K2_NS; ns++) {
        float4 v = *reinterpret_cast<const float4*>(&g_Mp[ns][b][c][d4]);
        s.x += v.x; s.y += v.y; s.z += v.z; s.w += v.w;
    }
    *reinterpret_cast<float4*>(&g_Msum[b][c][d4]) = s;
}

// ---------------------------------------------------------------------------
// K3 (mma): KVp[cs][b][m][e] = sum_{c in 128-split} Msum[b][c][m] * wv[e][c]
// grid (4 e-tiles, 8 b, 4 cs) = 128 blocks, 256 thr. Tile 64m x 128e, K-chunk 32.
// smem: sM[32][72] ([c][m], A read transposed), sW[128][36] ([e][c])
// ---------------------------------------------------------------------------
__global__ __launch_bounds__(256) void k3_mma(const float* __restrict__ wv)
{
    const int b  = blockIdx.y;
    const int e0 = blockIdx.x * 128;
    const int cs = blockIdx.z;
    const int cb0 = cs * 128;
    const int tid = threadIdx.x;
    const int wid = tid >> 5, lane = tid & 31;
    const int g = lane >> 2, tig = lane & 3;
    const int wm0 = (wid >> 2) * 32;   // 2 m-warps
    const int we0 = (wid & 3) * 32;    // 4 e-warps

    __shared__ float sM[32 * 72];      // [c][m] stride 72
    __shared__ float sW[128 * 36];     // [e][c] stride 36
    const uint32_t* sMu = reinterpret_cast<const uint32_t*>(sM);
    const uint32_t* sWu = reinterpret_cast<const uint32_t*>(sW);

    float4 acc[2][4];
#pragma unroll
    for (int i = 0; i < 2; i++)
#pragma unroll
        for (int j = 0; j < 4; j++) acc[i][j] = make_float4(0.f, 0.f, 0.f, 0.f);

    for (int cc = 0; cc < 128; cc += 32) {
        const int ca = cb0 + cc;
        // Msum tile: 32 c x 64 m = 512 float4
#pragma unroll
        for (int i = 0; i < 2; i++) {
            int idx = tid + i * 256;
            int c = idx >> 4;
            int m = (idx & 15) << 2;
            float4 v = *reinterpret_cast<const float4*>(&g_Msum[b][ca + c][m]);
            *reinterpret_cast<float4*>(&sM[c * 72 + m]) = v;
        }
        // wv tile: 128 e x 32 c = 1024 float4
#pragma unroll
        for (int i = 0; i < 4; i++) {
            int idx = tid + i * 256;
            int e = idx >> 3;
            int k = (idx & 7) << 2;
            float4 v = *reinterpret_cast<const float4*>(
                wv + (size_t)(e0 + e) * CC + ca + k);
            *reinterpret_cast<float4*>(&sW[e * 36 + k]) = v;
        }
        __syncthreads();
#pragma unroll
        for (int ks = 0; ks < 32; ks += 8) {
            uint32_t a[2][4];
#pragma unroll
            for (int i = 0; i < 2; i++) {
                int r = wm0 + i * 16 + g;
                a[i][0] = sMu[(ks + tig) * 72 + r];
                a[i][1] = sMu[(ks + tig) * 72 + r + 8];
                a[i][2] = sMu[(ks + tig + 4) * 72 + r];
                a[i][3] = sMu[(ks + tig + 4) * 72 + r + 8];
            }
#pragma unroll
            for (int j = 0; j < 4; j++) {
                int e = we0 + j * 8 + g;
                uint32_t b0 = sWu[e * 36 + ks + tig];
                uint32_t b1 = sWu[e * 36 + ks + tig + 4];
#pragma unroll
                for (int i = 0; i < 2; i++)
                    mma_tf32(acc[i][j], a[i][0], a[i][1], a[i][2], a[i][3], b0, b1);
            }
        }
        __syncthreads();
    }
#pragma unroll
    for (int i = 0; i < 2; i++) {
        int m0 = wm0 + i * 16 + g;
#pragma unroll
        for (int j = 0; j < 4; j++) {
            int e = e0 + we0 + j * 8 + 2 * tig;
            *reinterpret_cast<float2*>(&g_KVp[cs][b][m0][e])     = make_float2(acc[i][j].x, acc[i][j].y);
            *reinterpret_cast<float2*>(&g_KVp[cs][b][m0 + 8][e]) = make_float2(acc[i][j].z, acc[i][j].w);
        }
    }
}

// ---------------------------------------------------------------------------
// K3c: KV = sum_cs KVp + Ksum (x) bv.  64K float4; grid 256 x 256
// ---------------------------------------------------------------------------
__global__ __launch_bounds__(256) void k3c_merge(const float* __restrict__ bv)
{
    const int f = blockIdx.x * 256 + threadIdx.x;
    const int b = f >> 13;
    const int r = f & 8191;
    const int m = r >> 7;
    const int e4 = (r & 127) << 2;

    float4 s0 = *reinterpret_cast<const float4*>(&g_KVp[0][b][m][e4]);
    float4 s1 = *reinterpret_cast<const float4*>(&g_KVp[1][b][m][e4]);
    float4 s2 = *reinterpret_cast<const float4*>(&g_KVp[2][b][m][e4]);
    float4 s3 = *reinterpret_cast<const float4*>(&g_KVp[3][b][m][e4]);
    float4 bb = *reinterpret_cast<const float4*>(bv + e4);
    const float ks = g_Ksum[b][m];
    float4 o;
    o.x = s0.x + s1.x + s2.x + s3.x + ks * bb.x;
    o.y = s0.y + s1.y + s2.y + s3.y + ks * bb.y;
    o.z = s0.z + s1.z + s2.z + s3.z + ks * bb.z;
    o.w = s0.w + s1.w + s2.w + s3.w + ks * bb.w;
    *reinterpret_cast<float4*>(&g_KV[b][m][e4]) = o;
}

// ---------------------------------------------------------------------------
// K4 (mma): out[b][c][n] = x + gamma * norm[n] * sum_d Qf[d][n]*KV[d][c]
// grid (32 n-tiles, 4 c-tiles, 8 b), 256 thr. Tile 128c x 128n, K=64.
// dyn smem: sQ[64][136] + sV[64][136] (both read as tig-row fragments)
// ---------------------------------------------------------------------------
#define K4_SMEM (2 * 64 * 136 * 4)

__global__ __launch_bounds__(256) void k4_out(
    const float* __restrict__ x, const float* __restrict__ gamma,
    float* __restrict__ out)
{
    const int b  = blockIdx.z;
    const int n0 = blockIdx.x * 128;
    const int c0 = blockIdx.y * 128;
    const int tid = threadIdx.x;
    const int wid = tid >> 5, lane = tid & 31;
    const int g = lane >> 2, tig = lane & 3;
    const int wc0 = (wid >> 1) * 32;
    const int wn0 = (wid & 1) * 64;

    extern __shared__ float smem[];
    float* sQ = smem;               // [d][n] stride 136
    float* sV = smem + 64 * 136;    // [d][c] stride 136
    const uint32_t* sQu = reinterpret_cast<const uint32_t*>(sQ);
    const uint32_t* sVu = reinterpret_cast<const uint32_t*>(sV);
    __shared__ float snorm[128];
    __shared__ float sKs[64];

#pragma unroll
    for (int i = 0; i < 8; i++) {
        int idx = tid + i * 256;
        int d = idx >> 5;
        int j = (idx & 31) << 2;
        float4 v = *reinterpret_cast<const float4*>(&g_Qf[b][d][n0 + j]);
        *reinterpret_cast<float4*>(&sQ[d * 136 + j]) = v;
    }
#pragma unroll
    for (int i = 0; i < 8; i++) {
        int idx = tid + i * 256;
        int d = idx >> 5;
        int j = (idx & 31) << 2;
        float4 v = *reinterpret_cast<const float4*>(&g_KV[b][d][c0 + j]);
        *reinterpret_cast<float4*>(&sV[d * 136 + j]) = v;
    }
    if (tid < 64) sKs[tid] = g_Ksum[b][tid] + 1e-10f;
    __syncthreads();

    if (tid < 128) {
        float s = 0.f;
#pragma unroll
        for (int d = 0; d < 64; d++) s += sQ[d * 136 + tid] * sKs[d];
        snorm[tid] = 1.0f / s;
    }
    __syncthreads();

    float4 acc[2][8];
#pragma unroll
    for (int i = 0; i < 2; i++)
#pragma unroll
        for (int j = 0; j < 8; j++) acc[i][j] = make_float4(0.f, 0.f, 0.f, 0.f);

#pragma unroll
    for (int ks = 0; ks < 64; ks += 8) {
        uint32_t a[2][4];
#pragma unroll
        for (int i = 0; i < 2; i++) {
            int r = wc0 + i * 16 + g;
            a[i][0] = sVu[(ks + tig) * 136 + r];
            a[i][1] = sVu[(ks + tig) * 136 + r + 8];
            a[i][2] = sVu[(ks + tig + 4) * 136 + r];
            a[i][3] = sVu[(ks + tig + 4) * 136 + r + 8];
        }
#pragma unroll
        for (int j = 0; j < 8; j++) {
            int n = wn0 + j * 8 + g;
            uint32_t b0 = sQu[(ks + tig) * 136 + n];
            uint32_t b1 = sQu[(ks + tig + 4) * 136 + n];
#pragma unroll
            for (int i = 0; i < 2; i++)
                mma_tf32(acc[i][j], a[i][0], a[i][1], a[i][2], a[i][3], b0, b1);
        }
    }

    const float gm = gamma[0];
#pragma unroll
    for (int i = 0; i < 2; i++) {
        int r0 = c0 + wc0 + i * 16 + g;
        int r1 = r0 + 8;
#pragma unroll
        for (int j = 0; j < 8; j++) {
            int nl = wn0 + j * 8 + 2 * tig;
            float nm0 = snorm[nl], nm1 = snorm[nl + 1];
            size_t off0 = ((size_t)b * CC + r0) * NN + n0 + nl;
            size_t off1 = ((size_t)b * CC + r1) * NN + n0 + nl;
            float2 x0 = *reinterpret_cast<const float2*>(x + off0);
            float2 x1 = *reinterpret_cast<const float2*>(x + off1);
            float2 o0 = make_float2(x0.x + gm * acc[i][j].x * nm0,
                                    x0.y + gm * acc[i][j].y * nm1);
            float2 o1 = make_float2(x1.x + gm * acc[i][j].z * nm0,
                                    x1.y + gm * acc[i][j].w * nm1);
            *reinterpret_cast<float2*>(out + off0) = o0;
            *reinterpret_cast<float2*>(out + off1) = o1;
        }
    }
}

// ---------------------------------------------------------------------------
extern "C" void kernel_launch(void* const* d_in, const int* in_sizes, int n_in,
                              void* d_out, int out_size)
{
    const float* x     = (const float*)d_in[0];
    const float* wq    = (const float*)d_in[1];
    const float* bq    = (const float*)d_in[2];
    const float* wk    = (const float*)d_in[3];
    const float* bk    = (const float*)d_in[4];
    const float* wv    = (const float*)d_in[5];
    const float* bv    = (const float*)d_in[6];
    const float* gamma = (const float*)d_in[7];
    float* out = (float*)d_out;

    static bool attr_set = false;
    if (!attr_set) {
        cudaFuncSetAttribute(k1_qk,  cudaFuncAttributeMaxDynamicSharedMemorySize, K1_SMEM);
        cudaFuncSetAttribute(k2_mma, cudaFuncAttributeMaxDynamicSharedMemorySize, K2_SMEM);
        cudaFuncSetAttribute(k4_out, cudaFuncAttributeMaxDynamicSharedMemorySize, K4_SMEM);
        attr_set = true;
    }

    k1_qk<<<dim3(NN / 128, BB), 256, K1_SMEM>>>(x, wq, bq, wk, bk);
    k2a_ksum<<<dim3(DD, BB), 256>>>();
    k2_mma<<<dim3(CC / 128, BB, K2_NS), 256, K2_SMEM>>>(x);
    k2b_msum<<<256, 256>>>();
    k3_mma<<<dim3(CC / 128, BB, 4), 256>>>(wv);
    k3c_merge<<<256, 256>>>(bv);
    k4_out<<<dim3(NN / 128, CC / 128, BB), 256, K4_SMEM>>>(x, gamma, out);
}